// round 2
// baseline (speedup 1.0000x reference)
#include <cuda_runtime.h>

// KANLayer: out[b,o] = sum_i [ bias_w[o,i]*leaky(x[b,i]) + layer_w[o,i]*(edge_mlp_{o,i}(x[b,i])) ]
// edge MLP: h1 = leaky(x*W1+b1) [H]; h2 = leaky(W2@h1 + b2) [H]; e = W3.h2 + b3
// B=1024, I=64, O=64, H=32.

#define FMA2(d, a, b, c) \
    asm("fma.rn.f32x2 %0, %1, %2, %3;" : "=l"(d) : "l"(a), "l"(b), "l"(c))

constexpr int Bsz = 1024, Isz = 64, Osz = 64, Hsz = 32;
constexpr int BT = 128;        // batch rows per block
constexpr int THREADS = 256;

// smem layout (floats)
constexpr int XS_ELEMS  = BT * 65;          // x tile, padded stride 65
constexpr int H1_ELEMS  = Hsz * BT;         // h1, h-major [32][128]
constexpr int W2_F2     = Hsz * 33;         // duplicated W2 float2, [32][33]
constexpr int VEC_ELEMS = 4 * Hsz + 4;      // W1,b1,b2,W3 + b3,lw,bw
constexpr int SMEM_FLOATS = XS_ELEMS + H1_ELEMS + 2 * W2_F2 + VEC_ELEMS;
constexpr int SMEM_BYTES  = SMEM_FLOATS * 4;

__device__ __forceinline__ float leaky(float v) {
    return fmaxf(v, 0.0f) + 0.01f * fminf(v, 0.0f);
}

__global__ __launch_bounds__(THREADS) void kan_kernel(
    const float* __restrict__ x,  const float* __restrict__ W1,
    const float* __restrict__ b1, const float* __restrict__ W2,
    const float* __restrict__ b2, const float* __restrict__ W3,
    const float* __restrict__ b3, const float* __restrict__ lw,
    const float* __restrict__ bw, float* __restrict__ out)
{
    extern __shared__ float smem[];
    float*  x_s  = smem;                              // [128][65]
    float*  h1_s = x_s + XS_ELEMS;                    // [32][128]
    float2* w2s  = (float2*)(h1_s + H1_ELEMS);        // [32][33], (w,w) duplicated
    float*  W1_s = (float*)(w2s + W2_F2);
    float*  b1_s = W1_s + 32;
    float*  b2_s = W1_s + 64;
    float*  W3_s = W1_s + 96;
    float*  sc   = W1_s + 128;                        // [0]=b3 [1]=layer_w [2]=bias_w

    const int t  = threadIdx.x;
    const int o  = blockIdx.y;
    const int bt = blockIdx.x;

    // ---- load x tile once, coalesced ----
    const float* xg = x + (size_t)bt * BT * Isz;
    for (int g = t; g < BT * Isz; g += THREADS)
        x_s[(g >> 6) * 65 + (g & 63)] = xg[g];

    const int tx = t & 7,  ty = t >> 3;
    const int k0 = tx * 4, b0 = ty * 4;
    const int hb = t >> 7;       // 0/1: even/odd h rows for h1 stage
    const int bb = t & 127;      // this thread's b for h1 stage

    float oa0 = 0.f, oa1 = 0.f, oa2 = 0.f, oa3 = 0.f;

    for (int i = 0; i < Isz; ++i) {
        __syncthreads();  // previous iteration's readers done

        // ---- stage A: per-edge params -> smem ----
        const int e = o * Isz + i;
        if (t < 32) {
            const int p = e * Hsz + t;
            W1_s[t] = W1[p]; b1_s[t] = b1[p]; b2_s[t] = b2[p]; W3_s[t] = W3[p];
        } else if (t == 32) sc[0] = b3[e];
        else if (t == 33) sc[1] = lw[e];
        else if (t == 34) sc[2] = bw[e];
        {
            const float* W2g = W2 + (size_t)e * (Hsz * Hsz);
            const int h = t & 31, kb = t >> 5;
            #pragma unroll
            for (int r = 0; r < 4; ++r) {
                const int k = kb + r * 8;
                const float v = W2g[k * 32 + h];        // coalesced read
                w2s[h * 33 + k] = make_float2(v, v);    // duplicated for f32x2
            }
        }
        __syncthreads();

        // ---- stage B: h1 = leaky(x*W1 + b1), h-major ----
        {
            const float xv = x_s[bb * 65 + i];
            #pragma unroll
            for (int r = 0; r < 16; ++r) {
                const int h = 2 * r + hb;
                h1_s[h * 128 + bb] = leaky(fmaf(xv, W1_s[h], b1_s[h]));
            }
        }
        __syncthreads();

        // ---- stage C: GEMM 4b x 4k over h=32, packed f32x2 ----
        unsigned long long acc[8];
        #pragma unroll
        for (int j = 0; j < 8; ++j) acc[j] = 0ull;

        #pragma unroll
        for (int h = 0; h < 32; ++h) {
            const ulonglong2 av =
                *(const ulonglong2*)(h1_s + h * 128 + b0);   // b0..b0+3 (two f32x2)
            const unsigned long long* wr =
                (const unsigned long long*)(w2s + h * 33 + k0);
            #pragma unroll
            for (int kk = 0; kk < 4; ++kk) {
                const unsigned long long w = wr[kk];
                FMA2(acc[kk * 2],     av.x, w, acc[kk * 2]);
                FMA2(acc[kk * 2 + 1], av.y, w, acc[kk * 2 + 1]);
            }
        }

        // ---- epilogue: leaky(h2)+W3 dot, reduce over k lanes ----
        float pe0 = 0.f, pe1 = 0.f, pe2 = 0.f, pe3 = 0.f;
        #pragma unroll
        for (int kk = 0; kk < 4; ++kk) {
            const int k = k0 + kk;
            const float bbk = b2_s[k], w3 = W3_s[k];
            float l0, l1, l2, l3;
            asm("mov.b64 {%0,%1}, %2;" : "=f"(l0), "=f"(l1) : "l"(acc[kk * 2]));
            asm("mov.b64 {%0,%1}, %2;" : "=f"(l2), "=f"(l3) : "l"(acc[kk * 2 + 1]));
            pe0 += leaky(l0 + bbk) * w3;
            pe1 += leaky(l1 + bbk) * w3;
            pe2 += leaky(l2 + bbk) * w3;
            pe3 += leaky(l3 + bbk) * w3;
        }
        #pragma unroll
        for (int m = 1; m < 8; m <<= 1) {
            pe0 += __shfl_xor_sync(0xffffffffu, pe0, m);
            pe1 += __shfl_xor_sync(0xffffffffu, pe1, m);
            pe2 += __shfl_xor_sync(0xffffffffu, pe2, m);
            pe3 += __shfl_xor_sync(0xffffffffu, pe3, m);
        }
        const float vb3 = sc[0], vlw = sc[1], vbw = sc[2];
        oa0 += vlw * (pe0 + vb3) + vbw * leaky(x_s[(b0 + 0) * 65 + i]);
        oa1 += vlw * (pe1 + vb3) + vbw * leaky(x_s[(b0 + 1) * 65 + i]);
        oa2 += vlw * (pe2 + vb3) + vbw * leaky(x_s[(b0 + 2) * 65 + i]);
        oa3 += vlw * (pe3 + vb3) + vbw * leaky(x_s[(b0 + 3) * 65 + i]);
    }

    if (tx == 0) {
        const int bg = bt * BT + b0;
        out[(bg + 0) * Osz + o] = oa0;
        out[(bg + 1) * Osz + o] = oa1;
        out[(bg + 2) * Osz + o] = oa2;
        out[(bg + 3) * Osz + o] = oa3;
    }
}

extern "C" void kernel_launch(void* const* d_in, const int* in_sizes, int n_in,
                              void* d_out, int out_size)
{
    const float* x  = (const float*)d_in[0];
    const float* W1 = (const float*)d_in[1];
    const float* b1 = (const float*)d_in[2];
    const float* W2 = (const float*)d_in[3];
    const float* b2 = (const float*)d_in[4];
    const float* W3 = (const float*)d_in[5];
    const float* b3 = (const float*)d_in[6];
    const float* lw = (const float*)d_in[7];
    const float* bw = (const float*)d_in[8];
    float* out = (float*)d_out;

    cudaFuncSetAttribute(kan_kernel, cudaFuncAttributeMaxDynamicSharedMemorySize,
                         SMEM_BYTES);
    dim3 grid(Bsz / BT, Osz);   // (8, 64)
    kan_kernel<<<grid, THREADS, SMEM_BYTES>>>(x, W1, b1, W2, b2, W3, b3, lw, bw, out);
}

// round 6
// speedup vs baseline: 3.8789x; 3.8789x over previous
#include <cuda_runtime.h>

// KANLayer: out[b,o] = sum_i [ bias_w[o,i]*leaky(x[b,i]) + layer_w[o,i]*edge_mlp_{o,i}(x[b,i]) ]
// B=1024, I=64, O=64, H=32.
// R2: FFMA2 packed along k (no W2 duplication), 4b x 8k register tile,
//     x served from L1 (no smem x tile), smem ~22KB -> ~6 blocks/SM.

#define FMA2(d, a, b, c) \
    asm("fma.rn.f32x2 %0, %1, %2, %3;" : "=l"(d) : "l"(a), "l"(b), "l"(c))
#define DUP2(d, f) \
    asm("mov.b64 %0, {%1, %1};" : "=l"(d) : "f"(f))

constexpr int Bsz = 1024, Isz = 64, Osz = 64, Hsz = 32;
constexpr int BT = 128;          // batch rows per block
constexpr int THREADS = 128;

constexpr int H1S = 132;         // h1 row stride (floats): 528B, mult of 16
constexpr int W2S = 36;          // w2 row stride (floats): 144B, mult of 16

__device__ __forceinline__ float leaky(float v) {
    return fmaxf(v, 0.0f) + 0.01f * fminf(v, 0.0f);
}

__global__ __launch_bounds__(THREADS) void kan_kernel(
    const float* __restrict__ x,  const float* __restrict__ W1,
    const float* __restrict__ b1, const float* __restrict__ W2,
    const float* __restrict__ b2, const float* __restrict__ W3,
    const float* __restrict__ b3, const float* __restrict__ lw,
    const float* __restrict__ bw, float* __restrict__ out)
{
    __shared__ float h1_s[Hsz * H1S];          // [32][132], b-contiguous rows
    __shared__ float w2f[Hsz * W2S];           // [h][k], k-contiguous (natural f32x2 pairs)
    __shared__ float W1_s[32], b1_s[32], b2_s[32], W3_s[32], sc[3];

    const int t  = threadIdx.x;
    const int o  = blockIdx.y;
    const int bt = blockIdx.x;

    const int tx = t & 3,  ty = t >> 2;        // 4 k-groups x 32 b-groups
    const int k0 = tx * 8, b0 = ty * 4;

    const float* xrow = x + (size_t)(bt * BT + t) * Isz;   // stage-B row (b = t)

    float oa0 = 0.f, oa1 = 0.f, oa2 = 0.f, oa3 = 0.f;

    for (int i = 0; i < Isz; ++i) {
        __syncthreads();   // previous iteration's GEMM readers done

        // ---- stage A: per-edge params -> smem ----
        const int e = o * Isz + i;
        if (t < 32) {
            const int p = e * Hsz + t;
            W1_s[t] = W1[p]; b1_s[t] = b1[p]; b2_s[t] = b2[p]; W3_s[t] = W3[p];
        } else if (t == 32) sc[0] = b3[e];
        else if (t == 33) sc[1] = lw[e];
        else if (t == 34) sc[2] = bw[e];
        {
            const float* W2g = W2 + (size_t)e * (Hsz * Hsz);
            #pragma unroll
            for (int r = 0; r < 8; ++r) {
                const int idx = t + r * THREADS;          // coalesced gmem read
                w2f[(idx & 31) * W2S + (idx >> 5)] = W2g[idx];  // [h][k]
            }
        }
        __syncthreads();

        // ---- stage B: h1[b=t][h] = leaky(x*W1 + b1), stored h-major ----
        {
            const float xv = xrow[i];
            #pragma unroll
            for (int h = 0; h < 32; ++h)
                h1_s[h * H1S + t] = leaky(fmaf(xv, W1_s[h], b1_s[h]));
        }
        __syncthreads();

        // ---- stage C: GEMM 4b x 8k over h=32, f32x2 packed along k ----
        unsigned long long acc[4][4];          // [b][kpair]
        #pragma unroll
        for (int b = 0; b < 4; ++b)
            #pragma unroll
            for (int p = 0; p < 4; ++p) acc[b][p] = 0ull;

        #pragma unroll
        for (int h = 0; h < 32; ++h) {
            const float4 av = *(const float4*)(h1_s + h * H1S + b0);
            unsigned long long a0, a1, a2, a3;
            DUP2(a0, av.x); DUP2(a1, av.y); DUP2(a2, av.z); DUP2(a3, av.w);
            const ulonglong2* wr = (const ulonglong2*)(w2f + h * W2S + k0);
            const ulonglong2 wlo = wr[0], whi = wr[1];     // 8 k as 4 f32x2 pairs
            FMA2(acc[0][0], a0, wlo.x, acc[0][0]);
            FMA2(acc[1][0], a1, wlo.x, acc[1][0]);
            FMA2(acc[2][0], a2, wlo.x, acc[2][0]);
            FMA2(acc[3][0], a3, wlo.x, acc[3][0]);
            FMA2(acc[0][1], a0, wlo.y, acc[0][1]);
            FMA2(acc[1][1], a1, wlo.y, acc[1][1]);
            FMA2(acc[2][1], a2, wlo.y, acc[2][1]);
            FMA2(acc[3][1], a3, wlo.y, acc[3][1]);
            FMA2(acc[0][2], a0, whi.x, acc[0][2]);
            FMA2(acc[1][2], a1, whi.x, acc[1][2]);
            FMA2(acc[2][2], a2, whi.x, acc[2][2]);
            FMA2(acc[3][2], a3, whi.x, acc[3][2]);
            FMA2(acc[0][3], a0, whi.y, acc[0][3]);
            FMA2(acc[1][3], a1, whi.y, acc[1][3]);
            FMA2(acc[2][3], a2, whi.y, acc[2][3]);
            FMA2(acc[3][3], a3, whi.y, acc[3][3]);
        }

        // ---- epilogue: h2 = leaky(.+b2), dot W3, reduce over 4 k-lanes ----
        float pe0 = 0.f, pe1 = 0.f, pe2 = 0.f, pe3 = 0.f;
        #pragma unroll
        for (int p = 0; p < 4; ++p) {
            const int k = k0 + 2 * p;
            const float bbl = b2_s[k], bbh = b2_s[k + 1];
            const float w3l = W3_s[k], w3h = W3_s[k + 1];
            float l0, h0v, l1, h1v, l2, h2v, l3, h3v;
            asm("mov.b64 {%0,%1}, %2;" : "=f"(l0), "=f"(h0v) : "l"(acc[0][p]));
            asm("mov.b64 {%0,%1}, %2;" : "=f"(l1), "=f"(h1v) : "l"(acc[1][p]));
            asm("mov.b64 {%0,%1}, %2;" : "=f"(l2), "=f"(h2v) : "l"(acc[2][p]));
            asm("mov.b64 {%0,%1}, %2;" : "=f"(l3), "=f"(h3v) : "l"(acc[3][p]));
            pe0 += leaky(l0 + bbl) * w3l + leaky(h0v + bbh) * w3h;
            pe1 += leaky(l1 + bbl) * w3l + leaky(h1v + bbh) * w3h;
            pe2 += leaky(l2 + bbl) * w3l + leaky(h2v + bbh) * w3h;
            pe3 += leaky(l3 + bbl) * w3l + leaky(h3v + bbh) * w3h;
        }
        #pragma unroll
        for (int m = 1; m < 4; m <<= 1) {
            pe0 += __shfl_xor_sync(0xffffffffu, pe0, m);
            pe1 += __shfl_xor_sync(0xffffffffu, pe1, m);
            pe2 += __shfl_xor_sync(0xffffffffu, pe2, m);
            pe3 += __shfl_xor_sync(0xffffffffu, pe3, m);
        }
        if (tx == 0) {
            const float vb3 = sc[0], vlw = sc[1], vbw = sc[2];
            const float* xb = x + (size_t)(bt * BT + b0) * Isz + i;
            oa0 += vlw * (pe0 + vb3) + vbw * leaky(xb[0]);
            oa1 += vlw * (pe1 + vb3) + vbw * leaky(xb[Isz]);
            oa2 += vlw * (pe2 + vb3) + vbw * leaky(xb[2 * Isz]);
            oa3 += vlw * (pe3 + vb3) + vbw * leaky(xb[3 * Isz]);
        }
    }

    if (tx == 0) {
        const int bg = bt * BT + b0;
        out[(bg + 0) * Osz + o] = oa0;
        out[(bg + 1) * Osz + o] = oa1;
        out[(bg + 2) * Osz + o] = oa2;
        out[(bg + 3) * Osz + o] = oa3;
    }
}

extern "C" void kernel_launch(void* const* d_in, const int* in_sizes, int n_in,
                              void* d_out, int out_size)
{
    const float* x  = (const float*)d_in[0];
    const float* W1 = (const float*)d_in[1];
    const float* b1 = (const float*)d_in[2];
    const float* W2 = (const float*)d_in[3];
    const float* b2 = (const float*)d_in[4];
    const float* W3 = (const float*)d_in[5];
    const float* b3 = (const float*)d_in[6];
    const float* lw = (const float*)d_in[7];
    const float* bw = (const float*)d_in[8];
    float* out = (float*)d_out;

    dim3 grid(Bsz / BT, Osz);   // (8, 64)
    kan_kernel<<<grid, THREADS>>>(x, W1, b1, W2, b2, W3, b3, lw, bw, out);
}

// round 7
// speedup vs baseline: 4.7818x; 1.2328x over previous
#include <cuda_runtime.h>

// KANLayer: out[b,o] = sum_i [ bias_w[o,i]*leaky(x[b,i]) + layer_w[o,i]*edge_mlp_{o,i}(x[b,i]) ]
// B=1024, I=64, O=64, H=32.
// R6: 8 rows x 8 k register tile (64-thread blocks) -> 4 LDS.128 per 32 FFMA2;
//     i-loop split 2 ways over grid.z with device-scratch partials + reduce kernel.

#define FMA2(d, a, b, c) \
    asm("fma.rn.f32x2 %0, %1, %2, %3;" : "=l"(d) : "l"(a), "l"(b), "l"(c))
#define DUP2(d, f) \
    asm("mov.b64 %0, {%1, %1};" : "=l"(d) : "f"(f))

constexpr int Bsz = 1024, Isz = 64, Osz = 64, Hsz = 32;
constexpr int BT = 128;          // batch rows per block
constexpr int THREADS = 64;
constexpr int ZSPLIT = 2;        // i-halves
constexpr int IPB = Isz / ZSPLIT;

constexpr int H1S = 132;         // h1 row stride (floats), 528B (16B-mult)
constexpr int W2S = 36;          // w2 row stride (floats), 144B (16B-mult)

__device__ float g_scratch[ZSPLIT * Bsz * Osz];   // partial outputs

__device__ __forceinline__ float leaky(float v) {
    return fmaxf(v, 0.0f) + 0.01f * fminf(v, 0.0f);
}

__global__ __launch_bounds__(THREADS) void kan_kernel(
    const float* __restrict__ x,  const float* __restrict__ W1,
    const float* __restrict__ b1, const float* __restrict__ W2,
    const float* __restrict__ b2, const float* __restrict__ W3,
    const float* __restrict__ b3, const float* __restrict__ lw,
    const float* __restrict__ bw)
{
    __shared__ float h1_s[Hsz * H1S];            // [32][132]
    __shared__ float w2f[Hsz * W2S];             // [h][k], k-contiguous
    __shared__ float W1_s[32], b1_s[32], b2_s[32], W3_s[32], sc[3];

    const int t  = threadIdx.x;
    const int o  = blockIdx.y;
    const int bt = blockIdx.x;
    const int z  = blockIdx.z;

    const int tx = t & 3,  ty = t >> 2;          // 4 k-groups x 16 row-groups
    const int k0 = tx * 8, b0 = ty * 8;

    const float* xr0 = x + (size_t)(bt * BT + t) * Isz;        // stage-B rows
    const float* xr1 = x + (size_t)(bt * BT + t + 64) * Isz;

    float oa[8];
    #pragma unroll
    for (int r = 0; r < 8; ++r) oa[r] = 0.f;

    const int i0 = z * IPB;
    for (int ii = 0; ii < IPB; ++ii) {
        const int i = i0 + ii;
        __syncthreads();

        // ---- stage A: per-edge params -> smem ----
        const int e = o * Isz + i;
        if (t < 32) {
            const int p = e * Hsz + t;
            W1_s[t] = W1[p]; b1_s[t] = b1[p]; b2_s[t] = b2[p]; W3_s[t] = W3[p];
        } else if (t == 32) sc[0] = b3[e];
        else if (t == 33) sc[1] = lw[e];
        else if (t == 34) sc[2] = bw[e];
        {
            const float* W2g = W2 + (size_t)e * (Hsz * Hsz);
            #pragma unroll
            for (int r = 0; r < 16; ++r) {
                const int idx = t + r * THREADS;            // coalesced
                w2f[(idx & 31) * W2S + (idx >> 5)] = W2g[idx];   // [h][k]
            }
        }
        __syncthreads();

        // ---- stage B: h1 for rows t and t+64 ----
        {
            const float x0 = xr0[i], x1 = xr1[i];
            #pragma unroll
            for (int h = 0; h < 32; ++h) {
                const float w = W1_s[h], bb = b1_s[h];
                h1_s[h * H1S + t]      = leaky(fmaf(x0, w, bb));
                h1_s[h * H1S + t + 64] = leaky(fmaf(x1, w, bb));
            }
        }
        __syncthreads();

        // ---- stage C: GEMM 8 rows x 8 k over h=32 ----
        unsigned long long acc[8][4];
        #pragma unroll
        for (int r = 0; r < 8; ++r)
            #pragma unroll
            for (int p = 0; p < 4; ++p) acc[r][p] = 0ull;

        #pragma unroll
        for (int h = 0; h < 32; ++h) {
            const float4 av0 = *(const float4*)(h1_s + h * H1S + b0);
            const float4 av1 = *(const float4*)(h1_s + h * H1S + b0 + 4);
            unsigned long long a0, a1, a2, a3, a4, a5, a6, a7;
            DUP2(a0, av0.x); DUP2(a1, av0.y); DUP2(a2, av0.z); DUP2(a3, av0.w);
            DUP2(a4, av1.x); DUP2(a5, av1.y); DUP2(a6, av1.z); DUP2(a7, av1.w);
            const ulonglong2* wr = (const ulonglong2*)(w2f + h * W2S + k0);
            const ulonglong2 wA = wr[0], wB = wr[1];    // 8 k = 4 f32x2 pairs
            FMA2(acc[0][0], a0, wA.x, acc[0][0]);
            FMA2(acc[1][0], a1, wA.x, acc[1][0]);
            FMA2(acc[2][0], a2, wA.x, acc[2][0]);
            FMA2(acc[3][0], a3, wA.x, acc[3][0]);
            FMA2(acc[4][0], a4, wA.x, acc[4][0]);
            FMA2(acc[5][0], a5, wA.x, acc[5][0]);
            FMA2(acc[6][0], a6, wA.x, acc[6][0]);
            FMA2(acc[7][0], a7, wA.x, acc[7][0]);
            FMA2(acc[0][1], a0, wA.y, acc[0][1]);
            FMA2(acc[1][1], a1, wA.y, acc[1][1]);
            FMA2(acc[2][1], a2, wA.y, acc[2][1]);
            FMA2(acc[3][1], a3, wA.y, acc[3][1]);
            FMA2(acc[4][1], a4, wA.y, acc[4][1]);
            FMA2(acc[5][1], a5, wA.y, acc[5][1]);
            FMA2(acc[6][1], a6, wA.y, acc[6][1]);
            FMA2(acc[7][1], a7, wA.y, acc[7][1]);
            FMA2(acc[0][2], a0, wB.x, acc[0][2]);
            FMA2(acc[1][2], a1, wB.x, acc[1][2]);
            FMA2(acc[2][2], a2, wB.x, acc[2][2]);
            FMA2(acc[3][2], a3, wB.x, acc[3][2]);
            FMA2(acc[4][2], a4, wB.x, acc[4][2]);
            FMA2(acc[5][2], a5, wB.x, acc[5][2]);
            FMA2(acc[6][2], a6, wB.x, acc[6][2]);
            FMA2(acc[7][2], a7, wB.x, acc[7][2]);
            FMA2(acc[0][3], a0, wB.y, acc[0][3]);
            FMA2(acc[1][3], a1, wB.y, acc[1][3]);
            FMA2(acc[2][3], a2, wB.y, acc[2][3]);
            FMA2(acc[3][3], a3, wB.y, acc[3][3]);
            FMA2(acc[4][3], a4, wB.y, acc[4][3]);
            FMA2(acc[5][3], a5, wB.y, acc[5][3]);
            FMA2(acc[6][3], a6, wB.y, acc[6][3]);
            FMA2(acc[7][3], a7, wB.y, acc[7][3]);
        }

        // ---- epilogue: h2 = leaky(.+b2), dot W3, reduce over 4 k-lanes ----
        float pe[8];
        #pragma unroll
        for (int r = 0; r < 8; ++r) pe[r] = 0.f;
        #pragma unroll
        for (int p = 0; p < 4; ++p) {
            const int k = k0 + 2 * p;
            const float bbl = b2_s[k], bbh = b2_s[k + 1];
            const float w3l = W3_s[k], w3h = W3_s[k + 1];
            #pragma unroll
            for (int r = 0; r < 8; ++r) {
                float lo, hi;
                asm("mov.b64 {%0,%1}, %2;" : "=f"(lo), "=f"(hi) : "l"(acc[r][p]));
                pe[r] += leaky(lo + bbl) * w3l + leaky(hi + bbh) * w3h;
            }
        }
        #pragma unroll
        for (int m = 1; m < 4; m <<= 1)
            #pragma unroll
            for (int r = 0; r < 8; ++r)
                pe[r] += __shfl_xor_sync(0xffffffffu, pe[r], m);

        if (tx == 0) {
            const float vb3 = sc[0], vlw = sc[1], vbw = sc[2];
            const float* xb = x + (size_t)(bt * BT + b0) * Isz + i;
            #pragma unroll
            for (int r = 0; r < 8; ++r)
                oa[r] += vlw * (pe[r] + vb3) + vbw * leaky(xb[(size_t)r * Isz]);
        }
    }

    if (tx == 0) {
        const int bg = bt * BT + b0;
        float* dst = g_scratch + (size_t)z * (Bsz * Osz);
        #pragma unroll
        for (int r = 0; r < 8; ++r)
            dst[(bg + r) * Osz + o] = oa[r];
    }
}

__global__ void reduce_kernel(float* __restrict__ out)
{
    const int j = blockIdx.x * 256 + threadIdx.x;
    out[j] = g_scratch[j] + g_scratch[j + Bsz * Osz];
}

extern "C" void kernel_launch(void* const* d_in, const int* in_sizes, int n_in,
                              void* d_out, int out_size)
{
    const float* x  = (const float*)d_in[0];
    const float* W1 = (const float*)d_in[1];
    const float* b1 = (const float*)d_in[2];
    const float* W2 = (const float*)d_in[3];
    const float* b2 = (const float*)d_in[4];
    const float* W3 = (const float*)d_in[5];
    const float* b3 = (const float*)d_in[6];
    const float* lw = (const float*)d_in[7];
    const float* bw = (const float*)d_in[8];
    float* out = (float*)d_out;

    dim3 grid(Bsz / BT, Osz, ZSPLIT);   // (8, 64, 2) = 1024 blocks
    kan_kernel<<<grid, THREADS>>>(x, W1, b1, W2, b2, W3, b3, lw, bw);
    reduce_kernel<<<(Bsz * Osz) / 256, 256>>>(out);
}